// round 7
// baseline (speedup 1.0000x reference)
#include <cuda_runtime.h>
#include <cuda_bf16.h>
#include <cstdint>

#define NN   100000
#define NPAD 100096
#define EE   600000
#define HH   128
#define CC   47
#define LL   3
#define EPSV 1e-5f

#define ASTR 136
#define BSTR 264
#define APLANE (128 * ASTR * 2)   // 34816 B
#define BPLANE (128 * BSTR * 2)   // 67584 B

#define SBS  512
#define SNB  ((NN + SBS - 1) / SBS)   // 196

// Scratch (device globals; no allocation allowed)
__device__ unsigned short g_hhi[NPAD * ASTR];
__device__ unsigned short g_hlo[NPAD * ASTR];
__device__ unsigned short g_ahi[NPAD * ASTR];
__device__ unsigned short g_alo[NPAD * ASTR];
__device__ unsigned short g_wbhi_in[128 * ASTR];
__device__ unsigned short g_wblo_in[128 * ASTR];
__device__ unsigned short g_wbhi_l[LL * 128 * BSTR];
__device__ unsigned short g_wblo_l[LL * 128 * BSTR];
__device__ int   g_ideg[NN];
__device__ int   g_rs[NN + 1];
__device__ int   g_bsum[SNB];
__device__ int   g_boff[SNB];
__device__ int   g_cursor[NN];
__device__ int   g_csrc[EE];

// ---------------------------------------------------------------------------
__device__ __forceinline__ uint32_t smem_u32(const void* p) {
    uint32_t a;
    asm("{ .reg .u64 t; cvta.to.shared.u64 t, %1; cvt.u32.u64 %0, t; }"
        : "=r"(a) : "l"(p));
    return a;
}
__device__ __forceinline__ void ldsm4(uint32_t* r, uint32_t addr) {
    asm volatile("ldmatrix.sync.aligned.m8n8.x4.shared.b16 {%0,%1,%2,%3}, [%4];"
                 : "=r"(r[0]), "=r"(r[1]), "=r"(r[2]), "=r"(r[3]) : "r"(addr));
}
__device__ __forceinline__ void mma16816(float* c, const uint32_t* a, const uint32_t* b) {
    asm volatile(
        "mma.sync.aligned.m16n8k16.row.col.f32.bf16.bf16.f32 "
        "{%0,%1,%2,%3}, {%4,%5,%6,%7}, {%8,%9}, {%0,%1,%2,%3};"
        : "+f"(c[0]), "+f"(c[1]), "+f"(c[2]), "+f"(c[3])
        : "r"(a[0]), "r"(a[1]), "r"(a[2]), "r"(a[3]), "r"(b[0]), "r"(b[1]));
}
__device__ __forceinline__ void split1(float x, unsigned short& hi, unsigned short& lo) {
    __nv_bfloat16 h = __float2bfloat16(x);
    float r = x - __bfloat162float(h);
    __nv_bfloat16 l = __float2bfloat16(r);
    hi = __bfloat16_as_ushort(h);
    lo = __bfloat16_as_ushort(l);
}
__device__ __forceinline__ float tof(unsigned short hi, unsigned short lo) {
    return __uint_as_float((uint32_t)hi << 16) + __uint_as_float((uint32_t)lo << 16);
}
__device__ __forceinline__ void cpa16(uint32_t dst, const void* src) {
    asm volatile("cp.async.cg.shared.global [%0], [%1], 16;" :: "r"(dst), "l"(src));
}
#define CP_COMMIT() asm volatile("cp.async.commit_group;" ::: "memory")
#define CP_WAIT0()  asm volatile("cp.async.wait_group 0;" ::: "memory")

// ---------------------------------------------------------------------------
// weight prep: pre-transposed, pre-split planes in exact smem layout
__global__ void k_prep_in(const float* __restrict__ W) {
    int i = blockIdx.x * blockDim.x + threadIdx.x;
    if (i >= 128 * ASTR) return;
    int n = i / ASTR, k = i - n * ASTR;
    unsigned short hi = 0, lo = 0;
    if (k < 128) split1(W[k * 128 + n], hi, lo);
    g_wbhi_in[i] = hi;
    g_wblo_in[i] = lo;
}

__global__ void k_prep_layer(const float* __restrict__ Wl, const float* __restrict__ Wr) {
    int l = blockIdx.y;
    int i = blockIdx.x * blockDim.x + threadIdx.x;
    if (i >= 128 * BSTR) return;
    int n = i / BSTR, k = i - n * BSTR;
    unsigned short hi = 0, lo = 0;
    if (k < 128) split1(Wl[(long long)l * HH * HH + k * 128 + n], hi, lo);
    else if (k < 256) split1(Wr[(long long)l * HH * HH + (k - 128) * 128 + n], hi, lo);
    long long o = (long long)l * 128 * BSTR + i;
    g_wbhi_l[o] = hi;
    g_wblo_l[o] = lo;
}

// ---------------------------------------------------------------------------
// CSR build
__global__ void k_zero_int(int* __restrict__ p, int n) {
    int i = blockIdx.x * blockDim.x + threadIdx.x;
    if (i < n) p[i] = 0;
}

__global__ void k_hist(const int* __restrict__ dst) {
    int e = blockIdx.x * blockDim.x + threadIdx.x;
    if (e < EE) atomicAdd(&g_ideg[dst[e]], 1);
}

__global__ void __launch_bounds__(SBS) k_blocksum() {
    __shared__ int s[SBS];
    int i = blockIdx.x * SBS + threadIdx.x;
    s[threadIdx.x] = (i < NN) ? g_ideg[i] : 0;
    __syncthreads();
    for (int off = SBS / 2; off > 0; off >>= 1) {
        if (threadIdx.x < off) s[threadIdx.x] += s[threadIdx.x + off];
        __syncthreads();
    }
    if (threadIdx.x == 0) g_bsum[blockIdx.x] = s[0];
}

__global__ void __launch_bounds__(256) k_scanb() {
    __shared__ int s[SNB];
    int t = threadIdx.x;
    if (t < SNB) s[t] = g_bsum[t];
    __syncthreads();
    if (t == 0) {
        int acc = 0;
        for (int b = 0; b < SNB; b++) { int v = s[b]; s[b] = acc; acc += v; }
        g_rs[NN] = EE;
    }
    __syncthreads();
    if (t < SNB) g_boff[t] = s[t];
}

__global__ void __launch_bounds__(SBS) k_localscan() {
    __shared__ int s[SBS];
    int i = blockIdx.x * SBS + threadIdx.x;
    int d = (i < NN) ? g_ideg[i] : 0;
    s[threadIdx.x] = d;
    __syncthreads();
    for (int off = 1; off < SBS; off <<= 1) {
        int t = (threadIdx.x >= off) ? s[threadIdx.x - off] : 0;
        __syncthreads();
        s[threadIdx.x] += t;
        __syncthreads();
    }
    if (i < NN) g_rs[i] = g_boff[blockIdx.x] + s[threadIdx.x] - d;
}

__global__ void k_fill(const int* __restrict__ src, const int* __restrict__ dst) {
    int e = blockIdx.x * blockDim.x + threadIdx.x;
    if (e >= EE) return;
    int d = dst[e];
    int pos = g_rs[d] + atomicAdd(&g_cursor[d], 1);
    g_csrc[pos] = src[e];
}

// ---------------------------------------------------------------------------
// gather mean: agg[n] = mean of h[src] over in-edges (one warp per node)
// reads h planes, writes agg planes (pre-split)
__global__ void __launch_bounds__(256) k_gather() {
    int w = (blockIdx.x * blockDim.x + threadIdx.x) >> 5;
    int lane = threadIdx.x & 31;
    if (w >= NN) return;
    int beg = g_rs[w], end = g_rs[w + 1];
    int c0 = 4 * lane;
    float a0 = 0.f, a1 = 0.f, a2 = 0.f, a3 = 0.f;
    for (int j = beg; j < end; j++) {
        long long rb = (long long)g_csrc[j] * ASTR + c0;
        ushort4 H = *(const ushort4*)&g_hhi[rb];
        ushort4 L = *(const ushort4*)&g_hlo[rb];
        a0 += tof(H.x, L.x); a1 += tof(H.y, L.y);
        a2 += tof(H.z, L.z); a3 += tof(H.w, L.w);
    }
    float inv = 1.0f / (float)max(end - beg, 1);
    a0 *= inv; a1 *= inv; a2 *= inv; a3 *= inv;
    ushort4 OH, OL;
    split1(a0, OH.x, OL.x); split1(a1, OH.y, OL.y);
    split1(a2, OH.z, OL.z); split1(a3, OH.w, OL.w);
    long long ob = (long long)w * ASTR + c0;
    *(ushort4*)&g_ahi[ob] = OH;
    *(ushort4*)&g_alo[ob] = OL;
}

// ---------------------------------------------------------------------------
// input GEMM (mma.sync bf16 3-term split): h = relu(bn(x@W+b))
// 512 threads, block tile 128x128, warp tile 16x64
extern "C" __global__ void __launch_bounds__(512)
k_in_mma(const float* __restrict__ x, const float* __restrict__ bias,
         const float* __restrict__ bng, const float* __restrict__ bnb,
         const float* __restrict__ bnm, const float* __restrict__ bnv) {
    extern __shared__ char sm[];
    float* scp = (float*)sm;
    float* shp = (float*)(sm + 512);
    const uint32_t OFF_AHI = 1024;
    const uint32_t OFF_ALO = OFF_AHI + APLANE;
    const uint32_t OFF_BHI = OFF_ALO + APLANE;
    const uint32_t OFF_BLO = OFF_BHI + APLANE;
    unsigned short* Ahi = (unsigned short*)(sm + OFF_AHI);
    unsigned short* Alo = (unsigned short*)(sm + OFF_ALO);
    int tid = threadIdx.x;
    int wid = tid >> 5, lane = tid & 31;
    uint32_t sbase = smem_u32(sm);

    // B planes: async bulk copy (pre-split, pre-transposed, padded layout)
    {
        const char* bh = (const char*)g_wbhi_in;
        const char* bl = (const char*)g_wblo_in;
        for (int i = tid * 16; i < APLANE; i += 512 * 16) {
            cpa16(sbase + OFF_BHI + i, bh + i);
            cpa16(sbase + OFF_BLO + i, bl + i);
        }
        CP_COMMIT();
    }

    if (tid < 128) {
        int c = tid;
        float s = bng[c] * rsqrtf(bnv[c] + EPSV);
        scp[c] = s;
        shp[c] = bnb[c] - bnm[c] * s + bias[c] * s;
    }

    // A = x tile (fp32 input, split here)
    int row0 = blockIdx.x * 128;
    const float4* x4 = (const float4*)x;
    for (int i = tid; i < 128 * 32; i += 512) {
        int r = i >> 5, c4 = i & 31;
        int k = 4 * c4;
        float4 v = make_float4(0.f, 0.f, 0.f, 0.f);
        int gr = row0 + r;
        if (gr < NN) v = __ldg(&x4[(long long)gr * 32 + c4]);
        ushort4 UH, UL;
        split1(v.x, UH.x, UL.x); split1(v.y, UH.y, UL.y);
        split1(v.z, UH.z, UL.z); split1(v.w, UH.w, UL.w);
        *(ushort4*)&Ahi[r * ASTR + k] = UH;
        *(ushort4*)&Alo[r * ASTR + k] = UL;
    }
    CP_WAIT0();
    __syncthreads();

    int wm = wid & 7, wn = wid >> 3;
    int mwarp = wm * 16, nwarp = wn * 64;
    float c[8][4];
#pragma unroll
    for (int nt = 0; nt < 8; nt++)
#pragma unroll
        for (int q = 0; q < 4; q++) c[nt][q] = 0.f;

    uint32_t sAhi = sbase + OFF_AHI, sAlo = sbase + OFF_ALO;
    uint32_t sBhi = sbase + OFF_BHI, sBlo = sbase + OFF_BLO;
    uint32_t a_row = (lane & 15);
    uint32_t a_koff = (lane >> 4) << 3;
    uint32_t b_row = ((lane >> 4) << 3) + (lane & 7);
    uint32_t b_koff = ((lane >> 3) & 1) << 3;

#pragma unroll 1
    for (int k0 = 0; k0 < 128; k0 += 16) {
        uint32_t ah[4], al[4];
        {
            uint32_t off = (mwarp + a_row) * (ASTR * 2) + (k0 + a_koff) * 2;
            ldsm4(ah, sAhi + off);
            ldsm4(al, sAlo + off);
        }
        uint32_t bh[8][2], bl[8][2];
#pragma unroll
        for (int g = 0; g < 4; g++) {
            uint32_t off = (nwarp + g * 16 + b_row) * (ASTR * 2) + (k0 + b_koff) * 2;
            uint32_t t[4];
            ldsm4(t, sBhi + off);
            bh[2 * g][0] = t[0]; bh[2 * g][1] = t[1];
            bh[2 * g + 1][0] = t[2]; bh[2 * g + 1][1] = t[3];
            ldsm4(t, sBlo + off);
            bl[2 * g][0] = t[0]; bl[2 * g][1] = t[1];
            bl[2 * g + 1][0] = t[2]; bl[2 * g + 1][1] = t[3];
        }
#pragma unroll
        for (int nt = 0; nt < 8; nt++) {
            mma16816(c[nt], ah, bh[nt]);
            mma16816(c[nt], ah, bl[nt]);
            mma16816(c[nt], al, bh[nt]);
        }
    }

    int rq = lane >> 2, cp = (lane & 3) * 2;
#pragma unroll
    for (int nt = 0; nt < 8; nt++) {
        int col = nwarp + nt * 8 + cp;
        float s0 = scp[col], s1 = scp[col + 1];
        float t0 = shp[col], t1 = shp[col + 1];
        int r0g = row0 + mwarp + rq;
        if (r0g < NN) {
            float o0 = fmaxf(fmaf(c[nt][0], s0, t0), 0.f);
            float o1 = fmaxf(fmaf(c[nt][1], s1, t1), 0.f);
            ushort2 OH, OL;
            split1(o0, OH.x, OL.x); split1(o1, OH.y, OL.y);
            long long ob = (long long)r0g * ASTR + col;
            *(ushort2*)&g_hhi[ob] = OH;
            *(ushort2*)&g_hlo[ob] = OL;
        }
        int r1g = r0g + 8;
        if (r1g < NN) {
            float o0 = fmaxf(fmaf(c[nt][2], s0, t0), 0.f);
            float o1 = fmaxf(fmaf(c[nt][3], s1, t1), 0.f);
            ushort2 OH, OL;
            split1(o0, OH.x, OL.x); split1(o1, OH.y, OL.y);
            long long ob = (long long)r1g * ASTR + col;
            *(ushort2*)&g_hhi[ob] = OH;
            *(ushort2*)&g_hlo[ob] = OL;
        }
    }
}

// ---------------------------------------------------------------------------
// layer GEMM: t = relu(bn([agg|h] @ [Wl;Wr] + bl)); h += t (in-place)
extern "C" __global__ void __launch_bounds__(512)
k_layer_mma(int l, const float* __restrict__ blv,
            const float* __restrict__ bng, const float* __restrict__ bnb,
            const float* __restrict__ bnm, const float* __restrict__ bnv) {
    extern __shared__ char sm[];
    float* scp = (float*)sm;
    float* shp = (float*)(sm + 512);
    const uint32_t OFF_AHI = 1024;
    const uint32_t OFF_ALO = OFF_AHI + APLANE;
    const uint32_t OFF_BHI = OFF_ALO + APLANE;
    const uint32_t OFF_BLO = OFF_BHI + BPLANE;
    int tid = threadIdx.x;
    int wid = tid >> 5, lane = tid & 31;
    uint32_t sbase = smem_u32(sm);
    int row0 = blockIdx.x * 128;

    // B planes + A chunk0 (agg): async copies
    {
        const char* bh = (const char*)(g_wbhi_l + (long long)l * 128 * BSTR);
        const char* bl = (const char*)(g_wblo_l + (long long)l * 128 * BSTR);
        for (int i = tid * 16; i < BPLANE; i += 512 * 16) {
            cpa16(sbase + OFF_BHI + i, bh + i);
            cpa16(sbase + OFF_BLO + i, bl + i);
        }
        const char* ah = (const char*)g_ahi + (long long)row0 * ASTR * 2;
        const char* al = (const char*)g_alo + (long long)row0 * ASTR * 2;
        for (int i = tid * 16; i < APLANE; i += 512 * 16) {
            cpa16(sbase + OFF_AHI + i, ah + i);
            cpa16(sbase + OFF_ALO + i, al + i);
        }
        CP_COMMIT();
    }

    if (tid < 128) {
        int c = tid;
        float s = bng[l * HH + c] * rsqrtf(bnv[l * HH + c] + EPSV);
        scp[c] = s;
        shp[c] = bnb[l * HH + c] - bnm[l * HH + c] * s + blv[l * HH + c] * s;
    }

    int wm = wid & 7, wn = wid >> 3;
    int mwarp = wm * 16, nwarp = wn * 64;
    float c[8][4];
#pragma unroll
    for (int nt = 0; nt < 8; nt++)
#pragma unroll
        for (int q = 0; q < 4; q++) c[nt][q] = 0.f;

    uint32_t sAhi = sbase + OFF_AHI, sAlo = sbase + OFF_ALO;
    uint32_t sBhi = sbase + OFF_BHI, sBlo = sbase + OFF_BLO;
    uint32_t a_row = (lane & 15);
    uint32_t a_koff = (lane >> 4) << 3;
    uint32_t b_row = ((lane >> 4) << 3) + (lane & 7);
    uint32_t b_koff = ((lane >> 3) & 1) << 3;

#pragma unroll 1
    for (int kc = 0; kc < 2; kc++) {
        if (kc == 1) {
            __syncthreads();   // all warps done with chunk0 A
            const char* ah = (const char*)g_hhi + (long long)row0 * ASTR * 2;
            const char* al = (const char*)g_hlo + (long long)row0 * ASTR * 2;
            for (int i = tid * 16; i < APLANE; i += 512 * 16) {
                cpa16(sAhi + i, ah + i);
                cpa16(sAlo + i, al + i);
            }
            CP_COMMIT();
        }
        CP_WAIT0();
        __syncthreads();

#pragma unroll 1
        for (int k0 = 0; k0 < 128; k0 += 16) {
            int kb = kc * 128 + k0;
            uint32_t ah[4], al[4];
            {
                uint32_t off = (mwarp + a_row) * (ASTR * 2) + (k0 + a_koff) * 2;
                ldsm4(ah, sAhi + off);
                ldsm4(al, sAlo + off);
            }
            uint32_t bh[8][2], bl[8][2];
#pragma unroll
            for (int g = 0; g < 4; g++) {
                uint32_t off = (nwarp + g * 16 + b_row) * (BSTR * 2) + (kb + b_koff) * 2;
                uint32_t t[4];
                ldsm4(t, sBhi + off);
                bh[2 * g][0] = t[0]; bh[2 * g][1] = t[1];
                bh[2 * g + 1][0] = t[2]; bh[2 * g + 1][1] = t[3];
                ldsm4(t, sBlo + off);
                bl[2 * g][0] = t[0]; bl[2 * g][1] = t[1];
                bl[2 * g + 1][0] = t[2]; bl[2 * g + 1][1] = t[3];
            }
#pragma unroll
            for (int nt = 0; nt < 8; nt++) {
                mma16816(c[nt], ah, bh[nt]);
                mma16816(c[nt], ah, bl[nt]);
                mma16816(c[nt], al, bh[nt]);
            }
        }
    }

    // epilogue: h += relu(bn(acc)), h stored as split planes
    int rq = lane >> 2, cp = (lane & 3) * 2;
#pragma unroll
    for (int nt = 0; nt < 8; nt++) {
        int col = nwarp + nt * 8 + cp;
        float s0 = scp[col], s1 = scp[col + 1];
        float t0 = shp[col], t1 = shp[col + 1];
        int r0g = row0 + mwarp + rq;
        if (r0g < NN) {
            long long ob = (long long)r0g * ASTR + col;
            ushort2 HH2 = *(const ushort2*)&g_hhi[ob];
            ushort2 HL2 = *(const ushort2*)&g_hlo[ob];
            float o0 = tof(HH2.x, HL2.x) + fmaxf(fmaf(c[nt][0], s0, t0), 0.f);
            float o1 = tof(HH2.y, HL2.y) + fmaxf(fmaf(c[nt][1], s1, t1), 0.f);
            ushort2 OH, OL;
            split1(o0, OH.x, OL.x); split1(o1, OH.y, OL.y);
            *(ushort2*)&g_hhi[ob] = OH;
            *(ushort2*)&g_hlo[ob] = OL;
        }
        int r1g = r0g + 8;
        if (r1g < NN) {
            long long ob = (long long)r1g * ASTR + col;
            ushort2 HH2 = *(const ushort2*)&g_hhi[ob];
            ushort2 HL2 = *(const ushort2*)&g_hlo[ob];
            float o0 = tof(HH2.x, HL2.x) + fmaxf(fmaf(c[nt][2], s0, t0), 0.f);
            float o1 = tof(HH2.y, HL2.y) + fmaxf(fmaf(c[nt][3], s1, t1), 0.f);
            ushort2 OH, OL;
            split1(o0, OH.x, OL.x); split1(o1, OH.y, OL.y);
            *(ushort2*)&g_hhi[ob] = OH;
            *(ushort2*)&g_hlo[ob] = OL;
        }
    }
}

// ---------------------------------------------------------------------------
// output GEMM: out = h @ out_W + out_b   [N,47]  (SIMT, small)
extern "C" __global__ void __launch_bounds__(256)
k_out_gemm(const float* __restrict__ W, const float* __restrict__ bias,
           float* __restrict__ out) {
    extern __shared__ float smf[];
    float* Ws = smf;              // 128*48
    float* As = smf + 128 * 48;   // 64*129
    int tid = threadIdx.y * 64 + threadIdx.x;

    for (int i = tid; i < 128 * CC; i += 256) {
        int k = i / CC, c = i - k * CC;
        Ws[k * 48 + c] = W[i];
    }
    int row0 = blockIdx.x * 64;
    for (int i = tid; i < 64 * 64; i += 256) {
        int r = i >> 6, c2 = (i & 63) * 2;
        int gr = row0 + r;
        float f0 = 0.f, f1 = 0.f;
        if (gr < NN) {
            long long ob = (long long)gr * ASTR + c2;
            ushort2 H = *(const ushort2*)&g_hhi[ob];
            ushort2 L = *(const ushort2*)&g_hlo[ob];
            f0 = tof(H.x, L.x);
            f1 = tof(H.y, L.y);
        }
        As[r * 129 + c2] = f0;
        As[r * 129 + c2 + 1] = f1;
    }
    __syncthreads();

    int r = threadIdx.x;
    int c0 = threadIdx.y * 12;
    float acc[12];
#pragma unroll
    for (int j = 0; j < 12; j++) acc[j] = 0.f;

#pragma unroll 4
    for (int k = 0; k < 128; k++) {
        float a = As[r * 129 + k];
#pragma unroll
        for (int j = 0; j < 12; j++)
            acc[j] = fmaf(a, Ws[k * 48 + c0 + j], acc[j]);
    }

    int gr = row0 + r;
    if (gr < NN) {
#pragma unroll
        for (int j = 0; j < 12; j++) {
            int col = c0 + j;
            if (col < CC) out[(long long)gr * CC + col] = acc[j] + bias[col];
        }
    }
}

// ---------------------------------------------------------------------------
extern "C" void kernel_launch(void* const* d_in, const int* in_sizes, int n_in,
                              void* d_out, int out_size) {
    const float* x     = (const float*)d_in[0];
    const float* in_W  = (const float*)d_in[1];
    const float* in_b  = (const float*)d_in[2];
    const float* ibn_g = (const float*)d_in[3];
    const float* ibn_b = (const float*)d_in[4];
    const float* ibn_m = (const float*)d_in[5];
    const float* ibn_v = (const float*)d_in[6];
    const float* Wl    = (const float*)d_in[7];
    const float* bl    = (const float*)d_in[8];
    const float* Wr    = (const float*)d_in[9];
    const float* bn_g  = (const float*)d_in[10];
    const float* bn_b  = (const float*)d_in[11];
    const float* bn_m  = (const float*)d_in[12];
    const float* bn_v  = (const float*)d_in[13];
    const float* out_W = (const float*)d_in[14];
    const float* out_b = (const float*)d_in[15];
    const int*   ei    = (const int*)d_in[16];
    const int* src = ei;
    const int* dst = ei + EE;
    float* out = (float*)d_out;

    static bool attr_done = false;
    size_t smem_in    = 1024 + 4ull * APLANE;                 // ~137 KB
    size_t smem_layer = 1024 + 2ull * APLANE + 2ull * BPLANE; // ~201 KB
    size_t smem_out   = (size_t)(128 * 48 + 64 * 129) * 4;
    if (!attr_done) {
        cudaFuncSetAttribute(k_in_mma, cudaFuncAttributeMaxDynamicSharedMemorySize, (int)smem_in);
        cudaFuncSetAttribute(k_layer_mma, cudaFuncAttributeMaxDynamicSharedMemorySize, (int)smem_layer);
        cudaFuncSetAttribute(k_out_gemm, cudaFuncAttributeMaxDynamicSharedMemorySize, (int)smem_out);
        attr_done = true;
    }

    int* d_ideg;   cudaGetSymbolAddress((void**)&d_ideg, g_ideg);
    int* d_cursor; cudaGetSymbolAddress((void**)&d_cursor, g_cursor);

    int gemm_grid = (NN + 127) / 128;  // 782
    int out_grid  = (NN + 63) / 64;    // 1563

    // weight prep (once per launch)
    k_prep_in<<<(128 * ASTR + 255) / 256, 256>>>(in_W);
    k_prep_layer<<<dim3((128 * BSTR + 255) / 256, LL), 256>>>(Wl, Wr);

    // CSR build
    k_zero_int<<<(NN + 255) / 256, 256>>>(d_ideg, NN);
    k_zero_int<<<(NN + 255) / 256, 256>>>(d_cursor, NN);
    k_hist<<<(EE + 255) / 256, 256>>>(dst);
    k_blocksum<<<SNB, SBS>>>();
    k_scanb<<<1, 256>>>();
    k_localscan<<<SNB, SBS>>>();
    k_fill<<<(EE + 255) / 256, 256>>>(src, dst);

    k_in_mma<<<gemm_grid, 512, smem_in>>>(x, in_b, ibn_g, ibn_b, ibn_m, ibn_v);

    for (int l = 0; l < LL; l++) {
        k_gather<<<(NN * 32 + 255) / 256, 256>>>();
        k_layer_mma<<<gemm_grid, 512, smem_layer>>>(l, bl, bn_g, bn_b, bn_m, bn_v);
    }

    k_out_gemm<<<out_grid, dim3(64, 4), smem_out>>>(out_W, out_b, out);
}

// round 8
// speedup vs baseline: 1.2143x; 1.2143x over previous
#include <cuda_runtime.h>
#include <cuda_bf16.h>
#include <cstdint>

#define NN   100000
#define EE   600000
#define HH   128
#define CC   47
#define LL   3
#define EPSV 1e-5f

#define ASTR 136
#define BSTR 264
#define APLANE (128 * ASTR * 2)   // 34816 B
#define BPLANE (128 * BSTR * 2)   // 67584 B

#define SBS  512
#define SNB  ((NN + SBS - 1) / SBS)   // 196

// Scratch (device globals; no allocation allowed)
__device__ float g_h[NN * HH];
__device__ float g_agg[NN * HH];
__device__ unsigned short g_wbhi_in[128 * ASTR];
__device__ unsigned short g_wblo_in[128 * ASTR];
__device__ unsigned short g_wbhi_l[LL * 128 * BSTR];
__device__ unsigned short g_wblo_l[LL * 128 * BSTR];
__device__ int   g_ideg[NN];
__device__ int   g_rs[NN + 1];
__device__ int   g_bsum[SNB];
__device__ int   g_boff[SNB];
__device__ int   g_cursor[NN];
__device__ int   g_csrc[EE];

// ---------------------------------------------------------------------------
__device__ __forceinline__ uint32_t smem_u32(const void* p) {
    uint32_t a;
    asm("{ .reg .u64 t; cvta.to.shared.u64 t, %1; cvt.u32.u64 %0, t; }"
        : "=r"(a) : "l"(p));
    return a;
}
__device__ __forceinline__ void ldsm4(uint32_t* r, uint32_t addr) {
    asm volatile("ldmatrix.sync.aligned.m8n8.x4.shared.b16 {%0,%1,%2,%3}, [%4];"
                 : "=r"(r[0]), "=r"(r[1]), "=r"(r[2]), "=r"(r[3]) : "r"(addr));
}
__device__ __forceinline__ void mma16816(float* c, const uint32_t* a, const uint32_t* b) {
    asm volatile(
        "mma.sync.aligned.m16n8k16.row.col.f32.bf16.bf16.f32 "
        "{%0,%1,%2,%3}, {%4,%5,%6,%7}, {%8,%9}, {%0,%1,%2,%3};"
        : "+f"(c[0]), "+f"(c[1]), "+f"(c[2]), "+f"(c[3])
        : "r"(a[0]), "r"(a[1]), "r"(a[2]), "r"(a[3]), "r"(b[0]), "r"(b[1]));
}
__device__ __forceinline__ void split1(float x, unsigned short& hi, unsigned short& lo) {
    __nv_bfloat16 h = __float2bfloat16(x);
    float r = x - __bfloat162float(h);
    __nv_bfloat16 l = __float2bfloat16(r);
    hi = __bfloat16_as_ushort(h);
    lo = __bfloat16_as_ushort(l);
}
__device__ __forceinline__ void cpa16(uint32_t dst, const void* src) {
    asm volatile("cp.async.cg.shared.global [%0], [%1], 16;" :: "r"(dst), "l"(src));
}
#define CP_COMMIT() asm volatile("cp.async.commit_group;" ::: "memory")
#define CP_WAIT0()  asm volatile("cp.async.wait_group 0;" ::: "memory")

// ---------------------------------------------------------------------------
// weight prep: pre-transposed, pre-split planes in exact smem layout
__global__ void k_prep_in(const float* __restrict__ W) {
    int i = blockIdx.x * blockDim.x + threadIdx.x;
    if (i >= 128 * ASTR) return;
    int n = i / ASTR, k = i - n * ASTR;
    unsigned short hi = 0, lo = 0;
    if (k < 128) split1(W[k * 128 + n], hi, lo);
    g_wbhi_in[i] = hi;
    g_wblo_in[i] = lo;
}

__global__ void k_prep_layer(const float* __restrict__ Wl, const float* __restrict__ Wr) {
    int l = blockIdx.y;
    int i = blockIdx.x * blockDim.x + threadIdx.x;
    if (i >= 128 * BSTR) return;
    int n = i / BSTR, k = i - n * BSTR;
    unsigned short hi = 0, lo = 0;
    if (k < 128) split1(Wl[(long long)l * HH * HH + k * 128 + n], hi, lo);
    else if (k < 256) split1(Wr[(long long)l * HH * HH + (k - 128) * 128 + n], hi, lo);
    long long o = (long long)l * 128 * BSTR + i;
    g_wbhi_l[o] = hi;
    g_wblo_l[o] = lo;
}

// ---------------------------------------------------------------------------
// CSR build
__global__ void k_zero2(int* __restrict__ a, int* __restrict__ b, int n) {
    int i = blockIdx.x * blockDim.x + threadIdx.x;
    if (i < n) { a[i] = 0; b[i] = 0; }
}

__global__ void k_hist(const int* __restrict__ dst) {
    int e = blockIdx.x * blockDim.x + threadIdx.x;
    if (e < EE) atomicAdd(&g_ideg[dst[e]], 1);
}

__global__ void __launch_bounds__(SBS) k_blocksum() {
    __shared__ int s[SBS];
    int i = blockIdx.x * SBS + threadIdx.x;
    s[threadIdx.x] = (i < NN) ? g_ideg[i] : 0;
    __syncthreads();
    for (int off = SBS / 2; off > 0; off >>= 1) {
        if (threadIdx.x < off) s[threadIdx.x] += s[threadIdx.x + off];
        __syncthreads();
    }
    if (threadIdx.x == 0) g_bsum[blockIdx.x] = s[0];
}

__global__ void __launch_bounds__(256) k_scanb() {
    __shared__ int s[SNB];
    int t = threadIdx.x;
    if (t < SNB) s[t] = g_bsum[t];
    __syncthreads();
    if (t == 0) {
        int acc = 0;
        for (int b = 0; b < SNB; b++) { int v = s[b]; s[b] = acc; acc += v; }
        g_rs[NN] = EE;
    }
    __syncthreads();
    if (t < SNB) g_boff[t] = s[t];
}

__global__ void __launch_bounds__(SBS) k_localscan() {
    __shared__ int s[SBS];
    int i = blockIdx.x * SBS + threadIdx.x;
    int d = (i < NN) ? g_ideg[i] : 0;
    s[threadIdx.x] = d;
    __syncthreads();
    for (int off = 1; off < SBS; off <<= 1) {
        int t = (threadIdx.x >= off) ? s[threadIdx.x - off] : 0;
        __syncthreads();
        s[threadIdx.x] += t;
        __syncthreads();
    }
    if (i < NN) g_rs[i] = g_boff[blockIdx.x] + s[threadIdx.x] - d;
}

__global__ void k_fill(const int* __restrict__ src, const int* __restrict__ dst) {
    int e = blockIdx.x * blockDim.x + threadIdx.x;
    if (e >= EE) return;
    int d = dst[e];
    int pos = g_rs[d] + atomicAdd(&g_cursor[d], 1);
    g_csrc[pos] = src[e];
}

// ---------------------------------------------------------------------------
// gather mean: agg[n] = mean of h[src] over in-edges (one warp per node)
__global__ void __launch_bounds__(256) k_gather() {
    int w = (blockIdx.x * blockDim.x + threadIdx.x) >> 5;
    int lane = threadIdx.x & 31;
    if (w >= NN) return;
    int beg = g_rs[w], end = g_rs[w + 1];
    const float4* h4 = (const float4*)g_h;
    float4 acc = make_float4(0.f, 0.f, 0.f, 0.f);
    int j = beg;
    for (; j + 1 < end; j += 2) {
        int s0 = g_csrc[j], s1 = g_csrc[j + 1];
        float4 v0 = __ldg(&h4[(long long)s0 * 32 + lane]);
        float4 v1 = __ldg(&h4[(long long)s1 * 32 + lane]);
        acc.x += v0.x + v1.x; acc.y += v0.y + v1.y;
        acc.z += v0.z + v1.z; acc.w += v0.w + v1.w;
    }
    if (j < end) {
        int s0 = g_csrc[j];
        float4 v0 = __ldg(&h4[(long long)s0 * 32 + lane]);
        acc.x += v0.x; acc.y += v0.y; acc.z += v0.z; acc.w += v0.w;
    }
    float inv = 1.0f / (float)max(end - beg, 1);
    acc.x *= inv; acc.y *= inv; acc.z *= inv; acc.w *= inv;
    ((float4*)g_agg)[(long long)w * 32 + lane] = acc;
}

// ---------------------------------------------------------------------------
// input GEMM (mma.sync bf16 3-term split): h = relu(bn(x@W+b))
// 512 threads, block tile 128x128, warp tile 16x64
extern "C" __global__ void __launch_bounds__(512)
k_in_mma(const float* __restrict__ x, const float* __restrict__ bias,
         const float* __restrict__ bng, const float* __restrict__ bnb,
         const float* __restrict__ bnm, const float* __restrict__ bnv) {
    extern __shared__ char sm[];
    float* scp = (float*)sm;
    float* shp = (float*)(sm + 512);
    const uint32_t OFF_AHI = 1024;
    const uint32_t OFF_ALO = OFF_AHI + APLANE;
    const uint32_t OFF_BHI = OFF_ALO + APLANE;
    const uint32_t OFF_BLO = OFF_BHI + APLANE;
    unsigned short* Ahi = (unsigned short*)(sm + OFF_AHI);
    unsigned short* Alo = (unsigned short*)(sm + OFF_ALO);
    int tid = threadIdx.x;
    int wid = tid >> 5, lane = tid & 31;
    uint32_t sbase = smem_u32(sm);

    // B planes: async bulk copy (pre-split, pre-transposed, padded layout)
    {
        const char* bh = (const char*)g_wbhi_in;
        const char* bl = (const char*)g_wblo_in;
        for (int i = tid * 16; i < APLANE; i += 512 * 16) {
            cpa16(sbase + OFF_BHI + i, bh + i);
            cpa16(sbase + OFF_BLO + i, bl + i);
        }
        CP_COMMIT();
    }

    if (tid < 128) {
        int c = tid;
        float s = bng[c] * rsqrtf(bnv[c] + EPSV);
        scp[c] = s;
        shp[c] = bnb[c] - bnm[c] * s + bias[c] * s;
    }

    // A = x tile (fp32 input, split here)
    int row0 = blockIdx.x * 128;
    const float4* x4 = (const float4*)x;
    for (int i = tid; i < 128 * 32; i += 512) {
        int r = i >> 5, c4 = i & 31;
        int k = 4 * c4;
        float4 v = make_float4(0.f, 0.f, 0.f, 0.f);
        int gr = row0 + r;
        if (gr < NN) v = __ldg(&x4[(long long)gr * 32 + c4]);
        ushort4 UH, UL;
        split1(v.x, UH.x, UL.x); split1(v.y, UH.y, UL.y);
        split1(v.z, UH.z, UL.z); split1(v.w, UH.w, UL.w);
        *(ushort4*)&Ahi[r * ASTR + k] = UH;
        *(ushort4*)&Alo[r * ASTR + k] = UL;
    }
    CP_WAIT0();
    __syncthreads();

    int wm = wid & 7, wn = wid >> 3;
    int mwarp = wm * 16, nwarp = wn * 64;
    float c[8][4];
#pragma unroll
    for (int nt = 0; nt < 8; nt++)
#pragma unroll
        for (int q = 0; q < 4; q++) c[nt][q] = 0.f;

    uint32_t sAhi = sbase + OFF_AHI, sAlo = sbase + OFF_ALO;
    uint32_t sBhi = sbase + OFF_BHI, sBlo = sbase + OFF_BLO;
    uint32_t a_row = (lane & 15);
    uint32_t a_koff = (lane >> 4) << 3;
    uint32_t b_row = ((lane >> 4) << 3) + (lane & 7);
    uint32_t b_koff = ((lane >> 3) & 1) << 3;

#pragma unroll 1
    for (int k0 = 0; k0 < 128; k0 += 16) {
        uint32_t ah[4], al[4];
        {
            uint32_t off = (mwarp + a_row) * (ASTR * 2) + (k0 + a_koff) * 2;
            ldsm4(ah, sAhi + off);
            ldsm4(al, sAlo + off);
        }
        uint32_t bh[8][2], bl[8][2];
#pragma unroll
        for (int g = 0; g < 4; g++) {
            uint32_t off = (nwarp + g * 16 + b_row) * (ASTR * 2) + (k0 + b_koff) * 2;
            uint32_t t[4];
            ldsm4(t, sBhi + off);
            bh[2 * g][0] = t[0]; bh[2 * g][1] = t[1];
            bh[2 * g + 1][0] = t[2]; bh[2 * g + 1][1] = t[3];
            ldsm4(t, sBlo + off);
            bl[2 * g][0] = t[0]; bl[2 * g][1] = t[1];
            bl[2 * g + 1][0] = t[2]; bl[2 * g + 1][1] = t[3];
        }
#pragma unroll
        for (int nt = 0; nt < 8; nt++) {
            mma16816(c[nt], ah, bh[nt]);
            mma16816(c[nt], ah, bl[nt]);
            mma16816(c[nt], al, bh[nt]);
        }
    }

    int rq = lane >> 2, cp = (lane & 3) * 2;
    float2* h2 = (float2*)g_h;
#pragma unroll
    for (int nt = 0; nt < 8; nt++) {
        int col = nwarp + nt * 8 + cp;
        float s0 = scp[col], s1 = scp[col + 1];
        float t0 = shp[col], t1 = shp[col + 1];
        int r0g = row0 + mwarp + rq;
        if (r0g < NN) {
            float2 o;
            o.x = fmaxf(fmaf(c[nt][0], s0, t0), 0.f);
            o.y = fmaxf(fmaf(c[nt][1], s1, t1), 0.f);
            h2[(long long)r0g * 64 + (col >> 1)] = o;
        }
        int r1g = r0g + 8;
        if (r1g < NN) {
            float2 o;
            o.x = fmaxf(fmaf(c[nt][2], s0, t0), 0.f);
            o.y = fmaxf(fmaf(c[nt][3], s1, t1), 0.f);
            h2[(long long)r1g * 64 + (col >> 1)] = o;
        }
    }
}

// ---------------------------------------------------------------------------
// layer GEMM: t = relu(bn([agg|h] @ [Wl;Wr] + bl)); h += t (in-place)
extern "C" __global__ void __launch_bounds__(512)
k_layer_mma(int l, const float* __restrict__ blv,
            const float* __restrict__ bng, const float* __restrict__ bnb,
            const float* __restrict__ bnm, const float* __restrict__ bnv) {
    extern __shared__ char sm[];
    float* scp = (float*)sm;
    float* shp = (float*)(sm + 512);
    const uint32_t OFF_AHI = 1024;
    const uint32_t OFF_ALO = OFF_AHI + APLANE;
    const uint32_t OFF_BHI = OFF_ALO + APLANE;
    const uint32_t OFF_BLO = OFF_BHI + BPLANE;
    unsigned short* Ahi = (unsigned short*)(sm + OFF_AHI);
    unsigned short* Alo = (unsigned short*)(sm + OFF_ALO);
    int tid = threadIdx.x;
    int wid = tid >> 5, lane = tid & 31;
    uint32_t sbase = smem_u32(sm);
    int row0 = blockIdx.x * 128;

    // B planes: async bulk copy of pre-split weights
    {
        const char* bh = (const char*)(g_wbhi_l + (long long)l * 128 * BSTR);
        const char* bl = (const char*)(g_wblo_l + (long long)l * 128 * BSTR);
        for (int i = tid * 16; i < BPLANE; i += 512 * 16) {
            cpa16(sbase + OFF_BHI + i, bh + i);
            cpa16(sbase + OFF_BLO + i, bl + i);
        }
        CP_COMMIT();
    }

    if (tid < 128) {
        int c = tid;
        float s = bng[l * HH + c] * rsqrtf(bnv[l * HH + c] + EPSV);
        scp[c] = s;
        shp[c] = bnb[l * HH + c] - bnm[l * HH + c] * s + blv[l * HH + c] * s;
    }

    int wm = wid & 7, wn = wid >> 3;
    int mwarp = wm * 16, nwarp = wn * 64;
    float c[8][4];
#pragma unroll
    for (int nt = 0; nt < 8; nt++)
#pragma unroll
        for (int q = 0; q < 4; q++) c[nt][q] = 0.f;

    uint32_t sAhi = sbase + OFF_AHI, sAlo = sbase + OFF_ALO;
    uint32_t sBhi = sbase + OFF_BHI, sBlo = sbase + OFF_BLO;
    uint32_t a_row = (lane & 15);
    uint32_t a_koff = (lane >> 4) << 3;
    uint32_t b_row = ((lane >> 4) << 3) + (lane & 7);
    uint32_t b_koff = ((lane >> 3) & 1) << 3;

    const float4* agg4 = (const float4*)g_agg;
    const float4* h4g = (const float4*)g_h;

#pragma unroll 1
    for (int kc = 0; kc < 2; kc++) {
        if (kc == 1) __syncthreads();
        for (int i = tid; i < 128 * 32; i += 512) {
            int r = i >> 5, c4 = i & 31;
            int k = 4 * c4;
            float4 v = make_float4(0.f, 0.f, 0.f, 0.f);
            int gr = row0 + r;
            if (gr < NN)
                v = (kc == 0) ? agg4[(long long)gr * 32 + c4]
                              : h4g[(long long)gr * 32 + c4];
            ushort4 UH, UL;
            split1(v.x, UH.x, UL.x); split1(v.y, UH.y, UL.y);
            split1(v.z, UH.z, UL.z); split1(v.w, UH.w, UL.w);
            *(ushort4*)&Ahi[r * ASTR + k] = UH;
            *(ushort4*)&Alo[r * ASTR + k] = UL;
        }
        if (kc == 0) CP_WAIT0();
        __syncthreads();

#pragma unroll 1
        for (int k0 = 0; k0 < 128; k0 += 16) {
            int kb = kc * 128 + k0;
            uint32_t ah[4], al[4];
            {
                uint32_t off = (mwarp + a_row) * (ASTR * 2) + (k0 + a_koff) * 2;
                ldsm4(ah, sAhi + off);
                ldsm4(al, sAlo + off);
            }
            uint32_t bh[8][2], bl[8][2];
#pragma unroll
            for (int g = 0; g < 4; g++) {
                uint32_t off = (nwarp + g * 16 + b_row) * (BSTR * 2) + (kb + b_koff) * 2;
                uint32_t t[4];
                ldsm4(t, sBhi + off);
                bh[2 * g][0] = t[0]; bh[2 * g][1] = t[1];
                bh[2 * g + 1][0] = t[2]; bh[2 * g + 1][1] = t[3];
                ldsm4(t, sBlo + off);
                bl[2 * g][0] = t[0]; bl[2 * g][1] = t[1];
                bl[2 * g + 1][0] = t[2]; bl[2 * g + 1][1] = t[3];
            }
#pragma unroll
            for (int nt = 0; nt < 8; nt++) {
                mma16816(c[nt], ah, bh[nt]);
                mma16816(c[nt], ah, bl[nt]);
                mma16816(c[nt], al, bh[nt]);
            }
        }
    }

    int rq = lane >> 2, cp = (lane & 3) * 2;
    float2* h2 = (float2*)g_h;
#pragma unroll
    for (int nt = 0; nt < 8; nt++) {
        int col = nwarp + nt * 8 + cp;
        float s0 = scp[col], s1 = scp[col + 1];
        float t0 = shp[col], t1 = shp[col + 1];
        int r0g = row0 + mwarp + rq;
        if (r0g < NN) {
            long long idx = (long long)r0g * 64 + (col >> 1);
            float2 ho = h2[idx];
            float2 o;
            o.x = ho.x + fmaxf(fmaf(c[nt][0], s0, t0), 0.f);
            o.y = ho.y + fmaxf(fmaf(c[nt][1], s1, t1), 0.f);
            h2[idx] = o;
        }
        int r1g = r0g + 8;
        if (r1g < NN) {
            long long idx = (long long)r1g * 64 + (col >> 1);
            float2 ho = h2[idx];
            float2 o;
            o.x = ho.x + fmaxf(fmaf(c[nt][2], s0, t0), 0.f);
            o.y = ho.y + fmaxf(fmaf(c[nt][3], s1, t1), 0.f);
            h2[idx] = o;
        }
    }
}

// ---------------------------------------------------------------------------
// output GEMM: out = h @ out_W + out_b   [N,47]  (SIMT, small)
extern "C" __global__ void __launch_bounds__(256)
k_out_gemm(const float* __restrict__ W, const float* __restrict__ bias,
           float* __restrict__ out) {
    extern __shared__ float smf[];
    float* Ws = smf;              // 128*48
    float* As = smf + 128 * 48;   // 64*129
    int tid = threadIdx.y * 64 + threadIdx.x;

    for (int i = tid; i < 128 * CC; i += 256) {
        int k = i / CC, c = i - k * CC;
        Ws[k * 48 + c] = W[i];
    }
    int row0 = blockIdx.x * 64;
    for (int i = tid; i < 64 * 128; i += 256) {
        int r = i >> 7, c = i & 127;
        int gr = row0 + r;
        As[r * 129 + c] = (gr < NN) ? g_h[(long long)gr * 128 + c] : 0.f;
    }
    __syncthreads();

    int r = threadIdx.x;
    int c0 = threadIdx.y * 12;
    float acc[12];
#pragma unroll
    for (int j = 0; j < 12; j++) acc[j] = 0.f;

#pragma unroll 4
    for (int k = 0; k < 128; k++) {
        float a = As[r * 129 + k];
#pragma unroll
        for (int j = 0; j < 12; j++)
            acc[j] = fmaf(a, Ws[k * 48 + c0 + j], acc[j]);
    }

    int gr = row0 + r;
    if (gr < NN) {
#pragma unroll
        for (int j = 0; j < 12; j++) {
            int col = c0 + j;
            if (col < CC) out[(long long)gr * CC + col] = acc[j] + bias[col];
        }
    }
}

// ---------------------------------------------------------------------------
extern "C" void kernel_launch(void* const* d_in, const int* in_sizes, int n_in,
                              void* d_out, int out_size) {
    const float* x     = (const float*)d_in[0];
    const float* in_W  = (const float*)d_in[1];
    const float* in_b  = (const float*)d_in[2];
    const float* ibn_g = (const float*)d_in[3];
    const float* ibn_b = (const float*)d_in[4];
    const float* ibn_m = (const float*)d_in[5];
    const float* ibn_v = (const float*)d_in[6];
    const float* Wl    = (const float*)d_in[7];
    const float* bl    = (const float*)d_in[8];
    const float* Wr    = (const float*)d_in[9];
    const float* bn_g  = (const float*)d_in[10];
    const float* bn_b  = (const float*)d_in[11];
    const float* bn_m  = (const float*)d_in[12];
    const float* bn_v  = (const float*)d_in[13];
    const float* out_W = (const float*)d_in[14];
    const float* out_b = (const float*)d_in[15];
    const int*   ei    = (const int*)d_in[16];
    const int* src = ei;
    const int* dst = ei + EE;
    float* out = (float*)d_out;

    static bool attr_done = false;
    size_t smem_in    = 1024 + 4ull * APLANE;                 // ~137 KB
    size_t smem_layer = 1024 + 2ull * APLANE + 2ull * BPLANE; // ~201 KB
    size_t smem_out   = (size_t)(128 * 48 + 64 * 129) * 4;
    if (!attr_done) {
        cudaFuncSetAttribute(k_in_mma, cudaFuncAttributeMaxDynamicSharedMemorySize, (int)smem_in);
        cudaFuncSetAttribute(k_layer_mma, cudaFuncAttributeMaxDynamicSharedMemorySize, (int)smem_layer);
        cudaFuncSetAttribute(k_out_gemm, cudaFuncAttributeMaxDynamicSharedMemorySize, (int)smem_out);
        attr_done = true;
    }

    int* d_ideg;   cudaGetSymbolAddress((void**)&d_ideg, g_ideg);
    int* d_cursor; cudaGetSymbolAddress((void**)&d_cursor, g_cursor);

    int gemm_grid = (NN + 127) / 128;  // 782
    int out_grid  = (NN + 63) / 64;    // 1563

    // weight prep (once per launch)
    k_prep_in<<<(128 * ASTR + 255) / 256, 256>>>(in_W);
    k_prep_layer<<<dim3((128 * BSTR + 255) / 256, LL), 256>>>(Wl, Wr);

    // CSR build
    k_zero2<<<(NN + 255) / 256, 256>>>(d_ideg, d_cursor, NN);
    k_hist<<<(EE + 255) / 256, 256>>>(dst);
    k_blocksum<<<SNB, SBS>>>();
    k_scanb<<<1, 256>>>();
    k_localscan<<<SNB, SBS>>>();
    k_fill<<<(EE + 255) / 256, 256>>>(src, dst);

    k_in_mma<<<gemm_grid, 512, smem_in>>>(x, in_b, ibn_g, ibn_b, ibn_m, ibn_v);

    for (int l = 0; l < LL; l++) {
        k_gather<<<(NN * 32 + 255) / 256, 256>>>();
        k_layer_mma<<<gemm_grid, 512, smem_layer>>>(l, bl, bn_g, bn_b, bn_m, bn_v);
    }

    k_out_gemm<<<out_grid, dim3(64, 4), smem_out>>>(out_W, out_b, out);
}